// round 9
// baseline (speedup 1.0000x reference)
#include <cuda_runtime.h>
#include <cuda_fp16.h>
#include <mma.h>
#include <math.h>

using namespace nvcuda;

#define N_NODES 40000
#define E_EDGES 640000
#define IN_F 128
#define OUT_F 32
#define HEADS 8
#define MCOLS (HEADS * OUT_F)   // 256

// Scratch (static device globals; no allocation allowed).
__device__ __align__(16) __half g_Mh[N_NODES * MCOLS];   // h @ W_msg[:128] fp16
__device__ __align__(16) float g_asrc[N_NODES * HEADS];
__device__ __align__(16) float g_adst[N_NODES * HEADS];
__device__ __align__(16) float g_sum[N_NODES * HEADS];   // softmax denominators
__device__ __align__(16) float g_attn[E_EDGES * HEADS];  // exp(score), src-CSR order
__device__ __align__(16) int   g_srcs[E_EDGES];          // src per CSR slot
__device__ __align__(16) int   g_dsts[E_EDGES];          // dst per CSR slot
__device__ __align__(16) float g_ex[E_EDGES];            // edge feat per CSR slot
__device__ __align__(16) int   g_cnt[N_NODES];           // out-degree histogram
__device__ __align__(16) int   g_off[N_NODES + 1];
__device__ __align__(16) int   g_cur[N_NODES];
__device__ __align__(16) float g_csrc[IN_F * HEADS];
__device__ __align__(16) float g_cdst[IN_F * HEADS];

// ---------------------------------------------------------------------------
__global__ void k_init(float* __restrict__ out) {
    int i = blockIdx.x * blockDim.x + threadIdx.x;
    if (i < N_NODES * OUT_F) out[i] = 0.f;
    if (i < N_NODES * HEADS) g_sum[i] = 0.f;
    if (i < N_NODES) g_cnt[i] = 0;
}

// ---------------------------------------------------------------------------
// fold W_node with attention vectors: c[i,h] = sum_f W_node[i, h*32+f] * att[h,f]
__global__ void k_coef(const float* __restrict__ Wn,
                       const float* __restrict__ att_s,
                       const float* __restrict__ att_d) {
    int t = threadIdx.x;             // 1024 threads: t = i*8 + h
    int i = t >> 3, hh = t & 7;
    float s1 = 0.f, s2 = 0.f;
    #pragma unroll
    for (int f = 0; f < OUT_F; f++) {
        float w = Wn[i * MCOLS + hh * OUT_F + f];
        s1 += w * att_s[hh * OUT_F + f];
        s2 += w * att_d[hh * OUT_F + f];
    }
    g_csrc[t] = s1;
    g_cdst[t] = s2;
}

// ---------------------------------------------------------------------------
// per-node attention pre-scores, tiled: block loads 64 h-rows into smem once.
// NOTE smem row stride 132 (multiple of 4 floats) so float4 row stores stay
// 16B-aligned; stride%32==4 keeps the 4-distinct-row reads conflict-free.
__global__ void __launch_bounds__(256) k_anode(const float* __restrict__ h) {
    __shared__ float hs[64][132];
    __shared__ float cs[IN_F * HEADS];
    __shared__ float cd[IN_F * HEADS];
    int tid = threadIdx.x;
    int n0 = blockIdx.x * 64;        // 625 blocks exact
    for (int i = tid; i < IN_F * HEADS; i += 256) {
        cs[i] = g_csrc[i];
        cd[i] = g_cdst[i];
    }
    int r = tid >> 2, cb = (tid & 3) * 32;
    const float* hr = h + (size_t)(n0 + r) * IN_F + cb;
    #pragma unroll
    for (int q = 0; q < 8; q++) {
        float4 v = *(const float4*)(hr + q * 4);
        *(float4*)&hs[r][cb + q * 4] = v;
    }
    __syncthreads();
    #pragma unroll
    for (int rep = 0; rep < 2; rep++) {
        int o = tid + rep * 256;     // 0..511
        int n = o >> 3, hh = o & 7;
        float s1 = 0.f, s2 = 0.f;
        #pragma unroll 8
        for (int i = 0; i < IN_F; i++) {
            float hv = hs[n][i];
            s1 += hv * cs[i * HEADS + hh];
            s2 += hv * cd[i * HEADS + hh];
        }
        g_asrc[(n0 + n) * HEADS + hh] = s1;
        g_adst[(n0 + n) * HEADS + hh] = s2;
    }
}

// ---------------------------------------------------------------------------
// Tensor-core GEMM: M[40000,256] = h[40000,128] @ W_msg[0:128,0:256], fp16 out.
__global__ void __launch_bounds__(256) k_gemm(const float* __restrict__ h,
                                              const float* __restrict__ Wm) {
    __shared__ __align__(32) __half Ah[64][48];
    __shared__ __align__(32) __half Bh[32][272];
    __shared__ __align__(16) float Cst[8][16][16];
    int tid = threadIdx.x;
    int wid = tid >> 5, lane = tid & 31;
    int wm = wid >> 2;
    int wn = wid & 3;
    int m0 = blockIdx.x * 64;

    wmma::fragment<wmma::accumulator, 16, 16, 16, float> c[2][4];
    #pragma unroll
    for (int i = 0; i < 2; i++)
        #pragma unroll
        for (int j = 0; j < 4; j++) wmma::fill_fragment(c[i][j], 0.f);

    int ar = tid >> 2;
    int ac = (tid & 3) * 8;
    int br = tid >> 3;
    int bc = (tid & 7) * 32;

    for (int k0 = 0; k0 < IN_F; k0 += 32) {
        const float* ag = h + (size_t)(m0 + ar) * IN_F + k0 + ac;
        float4 v0 = *(const float4*)ag;
        float4 v1 = *(const float4*)(ag + 4);
        __half2* ap = (__half2*)&Ah[ar][ac];
        ap[0] = __floats2half2_rn(v0.x, v0.y);
        ap[1] = __floats2half2_rn(v0.z, v0.w);
        ap[2] = __floats2half2_rn(v1.x, v1.y);
        ap[3] = __floats2half2_rn(v1.z, v1.w);
        const float* bg = Wm + (size_t)(k0 + br) * MCOLS + bc;
        __half2* bp = (__half2*)&Bh[br][bc];
        #pragma unroll
        for (int q = 0; q < 8; q++) {
            float4 bv = *(const float4*)(bg + q * 4);
            bp[q * 2]     = __floats2half2_rn(bv.x, bv.y);
            bp[q * 2 + 1] = __floats2half2_rn(bv.z, bv.w);
        }
        __syncthreads();
        #pragma unroll
        for (int kk = 0; kk < 32; kk += 16) {
            wmma::fragment<wmma::matrix_a, 16, 16, 16, __half, wmma::row_major> af[2];
            wmma::fragment<wmma::matrix_b, 16, 16, 16, __half, wmma::row_major> bf[4];
            #pragma unroll
            for (int i = 0; i < 2; i++)
                wmma::load_matrix_sync(af[i], &Ah[wm * 32 + i * 16][kk], 48);
            #pragma unroll
            for (int j = 0; j < 4; j++)
                wmma::load_matrix_sync(bf[j], &Bh[kk][wn * 64 + j * 16], 272);
            #pragma unroll
            for (int i = 0; i < 2; i++)
                #pragma unroll
                for (int j = 0; j < 4; j++)
                    wmma::mma_sync(c[i][j], af[i], bf[j], c[i][j]);
        }
        __syncthreads();
    }
    int rr = lane >> 1, cc = (lane & 1) * 8;
    #pragma unroll
    for (int i = 0; i < 2; i++)
        #pragma unroll
        for (int j = 0; j < 4; j++) {
            wmma::store_matrix_sync(&Cst[wid][0][0], c[i][j], 16, wmma::mem_row_major);
            __syncwarp();
            const float* sp = &Cst[wid][rr][cc];
            __half2 hv[4];
            #pragma unroll
            for (int q = 0; q < 4; q++)
                hv[q] = __floats2half2_rn(sp[q * 2], sp[q * 2 + 1]);
            int grow = m0 + wm * 32 + i * 16 + rr;
            int gcol = wn * 64 + j * 16 + cc;
            *(uint4*)(g_Mh + (size_t)grow * MCOLS + gcol) = *(uint4*)hv;
            __syncwarp();
        }
}

// ---------------------------------------------------------------------------
// out-degree histogram (by src)
__global__ void k_hist(const int* __restrict__ ei) {
    int e = blockIdx.x * blockDim.x + threadIdx.x;
    if (e < E_EDGES) atomicAdd(&g_cnt[ei[e]], 1);
}

// ---------------------------------------------------------------------------
// exclusive scan of g_cnt -> g_off, g_cur. Single block, 1024 threads x 40.
__global__ void k_scan() {
    __shared__ int part[1024];
    int t = threadIdx.x;
    int base = t * 40;
    int s = 0;
    #pragma unroll 8
    for (int i = 0; i < 40; i++) {
        int idx = base + i;
        s += (idx < N_NODES) ? g_cnt[idx] : 0;
    }
    part[t] = s;
    __syncthreads();
    for (int off = 1; off < 1024; off <<= 1) {
        int v = (t >= off) ? part[t - off] : 0;
        __syncthreads();
        part[t] += v;
        __syncthreads();
    }
    int run = (t > 0) ? part[t - 1] : 0;
    for (int i = 0; i < 40; i++) {
        int idx = base + i;
        if (idx < N_NODES) {
            g_off[idx] = run;
            g_cur[idx] = run;
            run += g_cnt[idx];
        }
    }
    if (t == 1023) g_off[N_NODES] = part[1023];
}

// ---------------------------------------------------------------------------
// edge pass (original order): score -> leaky relu -> exp; denominator via
// atomics; scatter (p[8], src, dst, x) into src-grouped CSR slot.
__global__ void k_score(const int* __restrict__ ei, const float* __restrict__ ef,
                        const float* __restrict__ We) {
    int e = blockIdx.x * blockDim.x + threadIdx.x;
    if (e >= E_EDGES) return;
    int s = ei[e];
    int d = ei[E_EDGES + e];
    float x = ef[e];

    float4 sa0 = *(const float4*)&g_asrc[s * HEADS];
    float4 sa1 = *(const float4*)&g_asrc[s * HEADS + 4];
    float4 da0 = *(const float4*)&g_adst[d * HEADS];
    float4 da1 = *(const float4*)&g_adst[d * HEADS + 4];
    float sv[8] = {sa0.x, sa0.y, sa0.z, sa0.w, sa1.x, sa1.y, sa1.z, sa1.w};
    float dv[8] = {da0.x, da0.y, da0.z, da0.w, da1.x, da1.y, da1.z, da1.w};

    float p[8];
    #pragma unroll
    for (int hh = 0; hh < HEADS; hh++) {
        float a = sv[hh] + dv[hh] + x * __ldg(&We[hh]);
        a = (a > 0.f) ? a : 0.2f * a;          // leaky relu
        p[hh] = __expf(a);
    }
    #pragma unroll
    for (int hh = 0; hh < HEADS; hh++)
        atomicAdd(&g_sum[d * HEADS + hh], p[hh]);

    int pos = atomicAdd(&g_cur[s], 1);
    float* ap = &g_attn[(size_t)pos * HEADS];
    *(float4*)ap       = make_float4(p[0], p[1], p[2], p[3]);
    *(float4*)(ap + 4) = make_float4(p[4], p[5], p[6], p[7]);
    g_srcs[pos] = s;
    g_dsts[pos] = d;
    g_ex[pos]   = x;
}

// ---------------------------------------------------------------------------
// final pass: warp per CSR slot (src-sorted!), lane = output feature.
// Consecutive warps share M[src] rows -> L1/L2 line reuse on the 512B gather.
__global__ void __launch_bounds__(512) k_out(const float* __restrict__ Wm,
                                             float* __restrict__ out) {
    int gw = (blockIdx.x * blockDim.x + threadIdx.x) >> 5;
    int lane = threadIdx.x & 31;
    if (gw >= E_EDGES) return;
    int s = g_srcs[gw];
    int d = g_dsts[gw];
    float x = g_ex[gw];

    float al = 0.f;
    if (lane < HEADS) {
        float sm = g_sum[d * HEADS + lane];
        al = __fdividef(g_attn[(size_t)gw * HEADS + lane], fmaxf(sm, 1e-12f));
    }

    const __half* Mrow = g_Mh + (size_t)s * MCOLS;
    const float* Wlast = Wm + (size_t)IN_F * MCOLS;
    float contrib = 0.f;
    #pragma unroll
    for (int hh = 0; hh < HEADS; hh++) {
        float a = __shfl_sync(0xffffffffu, al, hh);
        float mv = __half2float(Mrow[hh * OUT_F + lane]);
        contrib += a * (mv + x * __ldg(&Wlast[hh * OUT_F + lane]));
    }
    atomicAdd(&out[d * OUT_F + lane], contrib * 0.125f);
}

// ---------------------------------------------------------------------------
extern "C" void kernel_launch(void* const* d_in, const int* in_sizes, int n_in,
                              void* d_out, int out_size) {
    const float* h   = (const float*)d_in[0];
    const int*   ei  = (const int*)d_in[1];
    const float* ef  = (const float*)d_in[2];
    const float* Wn  = (const float*)d_in[3];
    const float* We  = (const float*)d_in[4];
    const float* Asw = (const float*)d_in[5];
    const float* Adw = (const float*)d_in[6];
    const float* Wm  = (const float*)d_in[7];
    float* out = (float*)d_out;

    k_init<<<(N_NODES * OUT_F + 255) / 256, 256>>>(out);
    k_coef<<<1, 1024>>>(Wn, Asw, Adw);
    k_anode<<<N_NODES / 64, 256>>>(h);
    k_gemm<<<N_NODES / 64, 256>>>(h, Wm);
    k_hist<<<(E_EDGES + 255) / 256, 256>>>(ei);
    k_scan<<<1, 1024>>>();
    k_score<<<(E_EDGES + 255) / 256, 256>>>(ei, ef, We);
    k_out<<<(E_EDGES * 32 + 511) / 512, 512>>>(Wm, out);
}

// round 10
// speedup vs baseline: 1.5524x; 1.5524x over previous
#include <cuda_runtime.h>
#include <cuda_fp16.h>
#include <mma.h>
#include <math.h>

using namespace nvcuda;

#define N_NODES 40000
#define E_EDGES 640000
#define IN_F 128
#define OUT_F 32
#define HEADS 8
#define MCOLS (HEADS * OUT_F)   // 256

// Scratch (static device globals; no allocation allowed).
__device__ __align__(16) __half g_Mh[N_NODES * MCOLS];   // h @ W_msg[:128] fp16
__device__ __align__(16) float g_asrc[N_NODES * HEADS];
__device__ __align__(16) float g_adst[N_NODES * HEADS];
__device__ __align__(16) float g_sum[N_NODES * HEADS];   // softmax denominators
__device__ __align__(16) float g_attn[E_EDGES * HEADS];  // exp(score), edge order
__device__ __align__(16) float g_csrc[IN_F * HEADS];
__device__ __align__(16) float g_cdst[IN_F * HEADS];

// ---------------------------------------------------------------------------
__global__ void k_init(float* __restrict__ out) {
    int i = blockIdx.x * blockDim.x + threadIdx.x;
    if (i < N_NODES * OUT_F) out[i] = 0.f;
    if (i < N_NODES * HEADS) g_sum[i] = 0.f;
}

// ---------------------------------------------------------------------------
// fold W_node with attention vectors: c[i,h] = sum_f W_node[i, h*32+f] * att[h,f]
__global__ void k_coef(const float* __restrict__ Wn,
                       const float* __restrict__ att_s,
                       const float* __restrict__ att_d) {
    int t = threadIdx.x;             // 1024 threads: t = i*8 + h
    int i = t >> 3, hh = t & 7;
    float s1 = 0.f, s2 = 0.f;
    #pragma unroll
    for (int f = 0; f < OUT_F; f++) {
        float w = Wn[i * MCOLS + hh * OUT_F + f];
        s1 += w * att_s[hh * OUT_F + f];
        s2 += w * att_d[hh * OUT_F + f];
    }
    g_csrc[t] = s1;
    g_cdst[t] = s2;
}

// ---------------------------------------------------------------------------
// per-node attention pre-scores, tiled: block loads 64 h-rows into smem once.
// smem row stride 132 (mult of 4 floats -> float4 stores aligned).
__global__ void __launch_bounds__(256) k_anode(const float* __restrict__ h) {
    __shared__ float hs[64][132];
    __shared__ float cs[IN_F * HEADS];
    __shared__ float cd[IN_F * HEADS];
    int tid = threadIdx.x;
    int n0 = blockIdx.x * 64;        // 625 blocks exact
    for (int i = tid; i < IN_F * HEADS; i += 256) {
        cs[i] = g_csrc[i];
        cd[i] = g_cdst[i];
    }
    int r = tid >> 2, cb = (tid & 3) * 32;
    const float* hr = h + (size_t)(n0 + r) * IN_F + cb;
    #pragma unroll
    for (int q = 0; q < 8; q++) {
        float4 v = *(const float4*)(hr + q * 4);
        *(float4*)&hs[r][cb + q * 4] = v;
    }
    __syncthreads();
    #pragma unroll
    for (int rep = 0; rep < 2; rep++) {
        int o = tid + rep * 256;     // 0..511
        int n = o >> 3, hh = o & 7;
        float s1 = 0.f, s2 = 0.f;
        #pragma unroll 8
        for (int i = 0; i < IN_F; i++) {
            float hv = hs[n][i];
            s1 += hv * cs[i * HEADS + hh];
            s2 += hv * cd[i * HEADS + hh];
        }
        g_asrc[(n0 + n) * HEADS + hh] = s1;
        g_adst[(n0 + n) * HEADS + hh] = s2;
    }
}

// ---------------------------------------------------------------------------
// Tensor-core GEMM: M[40000,256] = h[40000,128] @ W_msg[0:128,0:256], fp16 out.
// Software-pipelined: next k-tile's global loads issued before the MMA work
// on the current smem tile (overlaps LDG latency with tensor pipe).
__global__ void __launch_bounds__(256) k_gemm(const float* __restrict__ h,
                                              const float* __restrict__ Wm) {
    __shared__ __align__(32) __half Ah[64][48];
    __shared__ __align__(32) __half Bh[32][272];
    __shared__ __align__(16) float Cst[8][16][16];
    int tid = threadIdx.x;
    int wid = tid >> 5, lane = tid & 31;
    int wm = wid >> 2;
    int wn = wid & 3;
    int m0 = blockIdx.x * 64;

    wmma::fragment<wmma::accumulator, 16, 16, 16, float> c[2][4];
    #pragma unroll
    for (int i = 0; i < 2; i++)
        #pragma unroll
        for (int j = 0; j < 4; j++) wmma::fill_fragment(c[i][j], 0.f);

    int ar = tid >> 2;
    int ac = (tid & 3) * 8;
    int br = tid >> 3;
    int bc = (tid & 7) * 32;

    const float* agp = h + (size_t)(m0 + ar) * IN_F + ac;
    const float* bgp = Wm + (size_t)br * MCOLS + bc;

    // prologue: load k0=0 tile into regs
    float4 va0 = *(const float4*)(agp);
    float4 va1 = *(const float4*)(agp + 4);
    float4 vb[8];
    #pragma unroll
    for (int q = 0; q < 8; q++) vb[q] = *(const float4*)(bgp + q * 4);

    #pragma unroll
    for (int it = 0; it < 4; it++) {
        // regs -> smem (fp32 -> fp16)
        __half2* ap = (__half2*)&Ah[ar][ac];
        ap[0] = __floats2half2_rn(va0.x, va0.y);
        ap[1] = __floats2half2_rn(va0.z, va0.w);
        ap[2] = __floats2half2_rn(va1.x, va1.y);
        ap[3] = __floats2half2_rn(va1.z, va1.w);
        __half2* bp = (__half2*)&Bh[br][bc];
        #pragma unroll
        for (int q = 0; q < 8; q++) {
            bp[q * 2]     = __floats2half2_rn(vb[q].x, vb[q].y);
            bp[q * 2 + 1] = __floats2half2_rn(vb[q].z, vb[q].w);
        }
        __syncthreads();
        // prefetch next k-tile (overlaps with MMAs below)
        if (it < 3) {
            const float* ag = agp + (it + 1) * 32;
            const float* bg = bgp + (size_t)(it + 1) * 32 * MCOLS;
            va0 = *(const float4*)(ag);
            va1 = *(const float4*)(ag + 4);
            #pragma unroll
            for (int q = 0; q < 8; q++) vb[q] = *(const float4*)(bg + q * 4);
        }
        #pragma unroll
        for (int kk = 0; kk < 32; kk += 16) {
            wmma::fragment<wmma::matrix_a, 16, 16, 16, __half, wmma::row_major> af[2];
            wmma::fragment<wmma::matrix_b, 16, 16, 16, __half, wmma::row_major> bf[4];
            #pragma unroll
            for (int i = 0; i < 2; i++)
                wmma::load_matrix_sync(af[i], &Ah[wm * 32 + i * 16][kk], 48);
            #pragma unroll
            for (int j = 0; j < 4; j++)
                wmma::load_matrix_sync(bf[j], &Bh[kk][wn * 64 + j * 16], 272);
            #pragma unroll
            for (int i = 0; i < 2; i++)
                #pragma unroll
                for (int j = 0; j < 4; j++)
                    wmma::mma_sync(c[i][j], af[i], bf[j], c[i][j]);
        }
        __syncthreads();
    }
    int rr = lane >> 1, cc = (lane & 1) * 8;
    #pragma unroll
    for (int i = 0; i < 2; i++)
        #pragma unroll
        for (int j = 0; j < 4; j++) {
            wmma::store_matrix_sync(&Cst[wid][0][0], c[i][j], 16, wmma::mem_row_major);
            __syncwarp();
            const float* sp = &Cst[wid][rr][cc];
            __half2 hv[4];
            #pragma unroll
            for (int q = 0; q < 4; q++)
                hv[q] = __floats2half2_rn(sp[q * 2], sp[q * 2 + 1]);
            int grow = m0 + wm * 32 + i * 16 + rr;
            int gcol = wn * 64 + j * 16 + cc;
            *(uint4*)(g_Mh + (size_t)grow * MCOLS + gcol) = *(uint4*)hv;
            __syncwarp();
        }
}

// ---------------------------------------------------------------------------
// edge pass: score -> leaky relu -> exp (no max shift; bounded scores),
// store p coalesced in edge order; denominator via two v4 vector reductions.
__global__ void k_score(const int* __restrict__ ei, const float* __restrict__ ef,
                        const float* __restrict__ We) {
    int e = blockIdx.x * blockDim.x + threadIdx.x;
    if (e >= E_EDGES) return;
    int s = ei[e];
    int d = ei[E_EDGES + e];
    float x = ef[e];

    float4 sa0 = *(const float4*)&g_asrc[s * HEADS];
    float4 sa1 = *(const float4*)&g_asrc[s * HEADS + 4];
    float4 da0 = *(const float4*)&g_adst[d * HEADS];
    float4 da1 = *(const float4*)&g_adst[d * HEADS + 4];
    float sv[8] = {sa0.x, sa0.y, sa0.z, sa0.w, sa1.x, sa1.y, sa1.z, sa1.w};
    float dv[8] = {da0.x, da0.y, da0.z, da0.w, da1.x, da1.y, da1.z, da1.w};

    float p[8];
    #pragma unroll
    for (int hh = 0; hh < HEADS; hh++) {
        float a = sv[hh] + dv[hh] + x * __ldg(&We[hh]);
        a = (a > 0.f) ? a : 0.2f * a;          // leaky relu
        p[hh] = __expf(a);
    }
    float* ap = &g_attn[(size_t)e * HEADS];
    *(float4*)ap       = make_float4(p[0], p[1], p[2], p[3]);
    *(float4*)(ap + 4) = make_float4(p[4], p[5], p[6], p[7]);

    float* sp = &g_sum[d * HEADS];             // 32B-aligned (d*8 floats)
    asm volatile("red.global.add.v4.f32 [%0], {%1, %2, %3, %4};"
                 :: "l"(sp), "f"(p[0]), "f"(p[1]), "f"(p[2]), "f"(p[3])
                 : "memory");
    asm volatile("red.global.add.v4.f32 [%0], {%1, %2, %3, %4};"
                 :: "l"(sp + 4), "f"(p[4]), "f"(p[5]), "f"(p[6]), "f"(p[7])
                 : "memory");
}

// ---------------------------------------------------------------------------
// final pass: warp per edge (original order), lane = output feature.
// contrib[f] = sum_h alpha[h] * (M[src,h,f] + ef * W_msg[128, h*32+f])
__global__ void __launch_bounds__(512) k_out(const int* __restrict__ ei,
                                             const float* __restrict__ ef,
                                             const float* __restrict__ Wm,
                                             float* __restrict__ out) {
    int gw = (blockIdx.x * blockDim.x + threadIdx.x) >> 5;
    int lane = threadIdx.x & 31;
    if (gw >= E_EDGES) return;
    int s = ei[gw];
    int d = ei[E_EDGES + gw];
    float x = ef[gw];

    float al = 0.f;
    if (lane < HEADS) {
        float sm = g_sum[d * HEADS + lane];
        al = __fdividef(g_attn[(size_t)gw * HEADS + lane], fmaxf(sm, 1e-12f));
    }

    const __half* Mrow = g_Mh + (size_t)s * MCOLS;
    const float* Wlast = Wm + (size_t)IN_F * MCOLS;
    float contrib = 0.f;
    #pragma unroll
    for (int hh = 0; hh < HEADS; hh++) {
        float a = __shfl_sync(0xffffffffu, al, hh);
        float mv = __half2float(Mrow[hh * OUT_F + lane]);
        contrib += a * (mv + x * __ldg(&Wlast[hh * OUT_F + lane]));
    }
    atomicAdd(&out[d * OUT_F + lane], contrib * 0.125f);   // fold mean over heads
}

// ---------------------------------------------------------------------------
extern "C" void kernel_launch(void* const* d_in, const int* in_sizes, int n_in,
                              void* d_out, int out_size) {
    const float* h   = (const float*)d_in[0];
    const int*   ei  = (const int*)d_in[1];
    const float* ef  = (const float*)d_in[2];
    const float* Wn  = (const float*)d_in[3];
    const float* We  = (const float*)d_in[4];
    const float* Asw = (const float*)d_in[5];
    const float* Adw = (const float*)d_in[6];
    const float* Wm  = (const float*)d_in[7];
    float* out = (float*)d_out;

    k_init<<<(N_NODES * OUT_F + 255) / 256, 256>>>(out);
    k_coef<<<1, 1024>>>(Wn, Asw, Adw);
    k_anode<<<N_NODES / 64, 256>>>(h);
    k_gemm<<<N_NODES / 64, 256>>>(h, Wm);
    k_score<<<(E_EDGES + 255) / 256, 256>>>(ei, ef, We);
    k_out<<<(E_EDGES * 32 + 511) / 512, 512>>>(ei, ef, Wm, out);
}